// round 2
// baseline (speedup 1.0000x reference)
#include <cuda_runtime.h>
#include <cuda_bf16.h>
#include <math.h>

#define BB 2
#define SS 2048
#define HH 16
#define DKx 1024
#define DVx 1024
#define BSx (BB*SS)
#define LOG2E 1.4426950408889634f

__device__ __nv_bfloat16 g_xb [BSx*DKx];
__device__ __nv_bfloat16 g_Wqb[DKx*DKx];
__device__ __nv_bfloat16 g_Wkb[DKx*DKx];
__device__ __nv_bfloat16 g_Wvb[DKx*DKx];
__device__ __nv_bfloat16 g_Wdb[DKx*DKx];
__device__ __nv_bfloat16 g_mixb[HH*DKx];
__device__ __nv_bfloat16 g_q  [BSx*DKx];
__device__ __nv_bfloat16 g_k  [BSx*DKx];
__device__ __nv_bfloat16 g_v  [BSx*DVx];
__device__ float         g_cb [BSx*HH];
__device__ __nv_bfloat16 g_ctx[BSx*DVx];
__device__ float         g_res[BSx*DVx];

static __device__ __forceinline__ unsigned sptr(const void* p){
    return (unsigned)__cvta_generic_to_shared(p);
}
static __device__ __forceinline__ void ldm4(unsigned&r0,unsigned&r1,unsigned&r2,unsigned&r3,unsigned a){
    asm volatile("ldmatrix.sync.aligned.m8n8.x4.shared.b16 {%0,%1,%2,%3},[%4];\n"
        :"=r"(r0),"=r"(r1),"=r"(r2),"=r"(r3):"r"(a));
}
static __device__ __forceinline__ void ldm4t(unsigned&r0,unsigned&r1,unsigned&r2,unsigned&r3,unsigned a){
    asm volatile("ldmatrix.sync.aligned.m8n8.x4.trans.shared.b16 {%0,%1,%2,%3},[%4];\n"
        :"=r"(r0),"=r"(r1),"=r"(r2),"=r"(r3):"r"(a));
}
static __device__ __forceinline__ void mma16816(float* c,unsigned a0,unsigned a1,unsigned a2,unsigned a3,
                                                unsigned b0,unsigned b1){
    asm volatile("mma.sync.aligned.m16n8k16.row.col.f32.bf16.bf16.f32 "
        "{%0,%1,%2,%3},{%4,%5,%6,%7},{%8,%9},{%0,%1,%2,%3};\n"
        :"+f"(c[0]),"+f"(c[1]),"+f"(c[2]),"+f"(c[3])
        :"r"(a0),"r"(a1),"r"(a2),"r"(a3),"r"(b0),"r"(b1));
}
static __device__ __forceinline__ unsigned pack2(float lo,float hi){
    __nv_bfloat162 t=__floats2bfloat162_rn(lo,hi); return *(unsigned*)&t;
}

__global__ void cvt_k(const float* __restrict__ s,__nv_bfloat16* __restrict__ d,int n){
    int i=blockIdx.x*blockDim.x+threadIdx.x;
    if(i<n) d[i]=__float2bfloat16(s[i]);
}

// C[M,1024] = A[M,1024] @ B[1024,1024]^T ; mode<2: bf16 out (+bias); mode 2: f32 out=acc+bias+resid
__global__ void __launch_bounds__(256) gemm_k(const __nv_bfloat16* __restrict__ A,
        const __nv_bfloat16* __restrict__ Bw,const float* __restrict__ bias,
        const float* __restrict__ resid,void* outp,int mode){
    __shared__ __align__(16) __nv_bfloat16 as_[128*72];
    __shared__ __align__(16) __nv_bfloat16 bs_[128*72];
    const int m0=blockIdx.x*128,n0=blockIdx.y*128;
    const int tid=threadIdx.x,wr=tid>>5,ln=tid&31,g=ln>>2,tg=ln&3;
    const unsigned asb=sptr(as_),bsb=sptr(bs_);
    float acc[64];
#pragma unroll
    for(int i=0;i<64;i++) acc[i]=0.f;
    for(int c0=0;c0<1024;c0+=64){
        __syncthreads();
#pragma unroll
        for(int t=0;t<4;t++){
            int idx=tid+t*256,row=idx>>3,cv=(idx&7)*8;
            *(uint4*)((char*)as_+(row*72+cv)*2)=*(const uint4*)(A +(size_t)(m0+row)*1024+c0+cv);
            *(uint4*)((char*)bs_+(row*72+cv)*2)=*(const uint4*)(Bw+(size_t)(n0+row)*1024+c0+cv);
        }
        __syncthreads();
#pragma unroll
        for(int kk=0;kk<4;kk++){
            unsigned a0,a1,a2,a3;
            ldm4(a0,a1,a2,a3,asb+((wr*16+(ln&15))*72+kk*16+((ln>>4)<<3))*2);
#pragma unroll
            for(int nb=0;nb<8;nb++){
                unsigned b0,b1,b2,b3;
                int brow=nb*16+(ln&7)+((ln&16)?8:0),bcol=kk*16+((ln&8)?8:0);
                ldm4(b0,b1,b2,b3,bsb+(brow*72+bcol)*2);
                mma16816(acc+(2*nb  )*4,a0,a1,a2,a3,b0,b1);
                mma16816(acc+(2*nb+1)*4,a0,a1,a2,a3,b2,b3);
            }
        }
    }
    const int r0=m0+wr*16+g;
    if(mode==2){
        float* out=(float*)outp;
#pragma unroll
        for(int nf=0;nf<16;nf++){
            int col=n0+nf*8+2*tg;
            float b0=bias[col],b1=bias[col+1];
            *(float2*)(out+(size_t)r0*1024+col)=make_float2(
                acc[nf*4+0]+b0+resid[(size_t)r0*1024+col],
                acc[nf*4+1]+b1+resid[(size_t)r0*1024+col+1]);
            *(float2*)(out+(size_t)(r0+8)*1024+col)=make_float2(
                acc[nf*4+2]+b0+resid[(size_t)(r0+8)*1024+col],
                acc[nf*4+3]+b1+resid[(size_t)(r0+8)*1024+col+1]);
        }
    }else{
        __nv_bfloat16* out=(__nv_bfloat16*)outp;
#pragma unroll
        for(int nf=0;nf<16;nf++){
            int col=n0+nf*8+2*tg;
            float b0=bias?bias[col]:0.f,b1=bias?bias[col+1]:0.f;
            *(__nv_bfloat162*)(out+(size_t)r0*1024+col)=__floats2bfloat162_rn(acc[nf*4+0]+b0,acc[nf*4+1]+b1);
            *(__nv_bfloat162*)(out+(size_t)(r0+8)*1024+col)=__floats2bfloat162_rn(acc[nf*4+2]+b0,acc[nf*4+3]+b1);
        }
    }
}

__global__ void __launch_bounds__(128) cb_k(const float* __restrict__ x,const float* __restrict__ Wcb){
    int s=blockIdx.x;
    __shared__ float xr[1024];
    for(int t=threadIdx.x;t<1024;t+=128) xr[t]=x[(size_t)s*1024+t];
    __syncthreads();
    int w=threadIdx.x>>5,ln=threadIdx.x&31;
#pragma unroll
    for(int j=0;j<4;j++){
        int h=w*4+j;
        const float* wrow=Wcb+(size_t)h*1024;
        float sum=0.f;
        for(int c=ln;c<1024;c+=32) sum+=xr[c]*wrow[c];
#pragma unroll
        for(int off=16;off;off>>=1) sum+=__shfl_xor_sync(0xffffffffu,sum,off);
        if(ln==0) g_cb[(size_t)s*HH+h]=sum;
    }
}

// fused attention: grid (S/128, H, B), 256 thr (8 warps x 16 q-rows)
__global__ void __launch_bounds__(256,1) flash_k(){
    const int b=blockIdx.z,h=blockIdx.y,i0=blockIdx.x*128;
    __shared__ __align__(16) __nv_bfloat16 qs [128*72];  // q chunk / V tile
    __shared__ __align__(16) __nv_bfloat16 ks_[128*72];
    __shared__ float cbs[128];
    __shared__ __align__(4) __nv_bfloat16 msh[1024];
    const int tid=threadIdx.x,wr=tid>>5,ln=tid&31,g=ln>>2,tg=ln&3;
    const unsigned qsb=sptr(qs),ksb=sptr(ks_);
    {
        const unsigned* src=(const unsigned*)(g_mixb+(size_t)h*DKx);
        unsigned* dst=(unsigned*)msh;
        for(int t=tid;t<512;t+=256) dst[t]=src[t];
    }
    float sacc[64],octx[32];
    float rm0=-1e30f,rm1=-1e30f,rl0=0.f,rl1=0.f;
#pragma unroll
    for(int i=0;i<32;i++) octx[i]=0.f;
    const __nv_bfloat16* qg=g_q+(size_t)(b*SS+i0)*DKx;
    const __nv_bfloat16* kg=g_k+(size_t)(b*SS)*DKx;
    const __nv_bfloat16* vg=g_v+(size_t)(b*SS)*DVx;
    const __nv_bfloat162* m2=(const __nv_bfloat162*)msh;

    for(int jt=0;jt<16;jt++){
        const int j0=jt*128;
#pragma unroll
        for(int i=0;i<64;i++) sacc[i]=0.f;
        for(int c0=0;c0<DKx;c0+=64){
            __syncthreads();
#pragma unroll
            for(int t=0;t<4;t++){
                int idx=tid+t*256,row=idx>>3,cv=(idx&7)*8;
                *(uint4*)((char*)qs +(row*72+cv)*2)=*(const uint4*)(qg+(size_t)row*DKx+c0+cv);
                *(uint4*)((char*)ks_+(row*72+cv)*2)=*(const uint4*)(kg+(size_t)(j0+row)*DKx+c0+cv);
            }
            if(c0==0&&tid<128) cbs[tid]=g_cb[(size_t)(b*SS+j0+tid)*HH+h];
            __syncthreads();
#pragma unroll
            for(int kk=0;kk<4;kk++){
                unsigned a0,a1,a2,a3;
                ldm4(a0,a1,a2,a3,qsb+((wr*16+(ln&15))*72+kk*16+((ln>>4)<<3))*2);
                __nv_bfloat162 mm0=m2[(c0+kk*16)/2+tg],mm1=m2[(c0+kk*16)/2+4+tg];
                {__nv_bfloat162 t=__hmul2(*(__nv_bfloat162*)&a0,mm0);a0=*(unsigned*)&t;}
                {__nv_bfloat162 t=__hmul2(*(__nv_bfloat162*)&a1,mm0);a1=*(unsigned*)&t;}
                {__nv_bfloat162 t=__hmul2(*(__nv_bfloat162*)&a2,mm1);a2=*(unsigned*)&t;}
                {__nv_bfloat162 t=__hmul2(*(__nv_bfloat162*)&a3,mm1);a3=*(unsigned*)&t;}
#pragma unroll
                for(int nb=0;nb<8;nb++){
                    unsigned b0,b1,b2,b3;
                    int brow=nb*16+(ln&7)+((ln&16)?8:0),bcol=kk*16+((ln&8)?8:0);
                    ldm4(b0,b1,b2,b3,ksb+(brow*72+bcol)*2);
                    mma16816(sacc+(2*nb  )*4,a0,a1,a2,a3,b0,b1);
                    mma16816(sacc+(2*nb+1)*4,a0,a1,a2,a3,b2,b3);
                }
            }
        }
        // online softmax: rows wr*16+g and +8; cols reduce over tg (xor 1,2)
        float mx0=rm0,mx1=rm1;
#pragma unroll
        for(int nf=0;nf<16;nf++){
            float c0v=cbs[nf*8+2*tg],c1v=cbs[nf*8+2*tg+1];
            float* sp=sacc+nf*4;
            sp[0]=(sp[0]+c0v)*0.125f; sp[1]=(sp[1]+c1v)*0.125f;
            sp[2]=(sp[2]+c0v)*0.125f; sp[3]=(sp[3]+c1v)*0.125f;
            mx0=fmaxf(mx0,fmaxf(sp[0],sp[1]));
            mx1=fmaxf(mx1,fmaxf(sp[2],sp[3]));
        }
        mx0=fmaxf(mx0,__shfl_xor_sync(0xffffffffu,mx0,1));
        mx0=fmaxf(mx0,__shfl_xor_sync(0xffffffffu,mx0,2));
        mx1=fmaxf(mx1,__shfl_xor_sync(0xffffffffu,mx1,1));
        mx1=fmaxf(mx1,__shfl_xor_sync(0xffffffffu,mx1,2));
        float al0=exp2f((rm0-mx0)*LOG2E),al1=exp2f((rm1-mx1)*LOG2E);
        rm0=mx0; rm1=mx1;
        float ls0=0.f,ls1=0.f;
#pragma unroll
        for(int nf=0;nf<16;nf++){
            float* sp=sacc+nf*4;
            sp[0]=exp2f((sp[0]-mx0)*LOG2E); ls0+=sp[0];
            sp[1]=exp2f((sp[1]-mx0)*LOG2E); ls0+=sp[1];
            sp[2]=exp2f((sp[2]-mx1)*LOG2E); ls1+=sp[2];
            sp[3]=exp2f((sp[3]-mx1)*LOG2E); ls1+=sp[3];
        }
        ls0+=__shfl_xor_sync(0xffffffffu,ls0,1);
        ls0+=__shfl_xor_sync(0xffffffffu,ls0,2);
        ls1+=__shfl_xor_sync(0xffffffffu,ls1,1);
        ls1+=__shfl_xor_sync(0xffffffffu,ls1,2);
        rl0=rl0*al0+ls0; rl1=rl1*al1+ls1;
#pragma unroll
        for(int i=0;i<8;i++){
            octx[i*4+0]*=al0; octx[i*4+1]*=al0;
            octx[i*4+2]*=al1; octx[i*4+3]*=al1;
        }
        // V tile (head slice, 128x64) into qs; ctx += P @ V
        __syncthreads();
#pragma unroll
        for(int t=0;t<4;t++){
            int idx=tid+t*256,row=idx>>3,cv=(idx&7)*8;
            *(uint4*)((char*)qs+(row*72+cv)*2)=*(const uint4*)(vg+(size_t)(j0+row)*DVx+h*64+cv);
        }
        __syncthreads();
#pragma unroll
        for(int kb=0;kb<8;kb++){
            unsigned a0=pack2(sacc[(2*kb)*4+0],sacc[(2*kb)*4+1]);
            unsigned a1=pack2(sacc[(2*kb)*4+2],sacc[(2*kb)*4+3]);
            unsigned a2=pack2(sacc[(2*kb+1)*4+0],sacc[(2*kb+1)*4+1]);
            unsigned a3=pack2(sacc[(2*kb+1)*4+2],sacc[(2*kb+1)*4+3]);
#pragma unroll
            for(int vp=0;vp<4;vp++){
                unsigned b0,b1,b2,b3;
                int vrow=kb*16+(ln&7)+((ln&8)?8:0),vcol=vp*16+((ln&16)?8:0);
                ldm4t(b0,b1,b2,b3,qsb+(vrow*72+vcol)*2);
                mma16816(octx+(2*vp  )*4,a0,a1,a2,a3,b0,b1);
                mma16816(octx+(2*vp+1)*4,a0,a1,a2,a3,b2,b3);
            }
        }
    }
    float inv0=1.f/rl0,inv1=1.f/rl1;
    int r0=i0+wr*16+g;
    __nv_bfloat16* cg=g_ctx+(size_t)(b*SS)*DVx+h*64;
#pragma unroll
    for(int nb=0;nb<8;nb++){
        int col=nb*8+2*tg;
        *(__nv_bfloat162*)(cg+(size_t)r0*DVx+col)=
            __floats2bfloat162_rn(octx[nb*4+0]*inv0,octx[nb*4+1]*inv0);
        *(__nv_bfloat162*)(cg+(size_t)(r0+8)*DVx+col)=
            __floats2bfloat162_rn(octx[nb*4+2]*inv1,octx[nb*4+3]*inv1);
    }
}

__global__ void __launch_bounds__(256) ln_k(const float* __restrict__ gamma,
        const float* __restrict__ beta,float* __restrict__ out){
    int s=blockIdx.x,tid=threadIdx.x;
    const float* r=g_res+(size_t)s*1024;
    float sum=0.f,sq=0.f;
#pragma unroll
    for(int i=tid;i<1024;i+=256){ float v=r[i]; sum+=v; sq+=v*v; }
#pragma unroll
    for(int off=16;off;off>>=1){
        sum+=__shfl_xor_sync(0xffffffffu,sum,off);
        sq +=__shfl_xor_sync(0xffffffffu,sq ,off);
    }
    __shared__ float ss[8],sv[8];
    if((tid&31)==0){ ss[tid>>5]=sum; sv[tid>>5]=sq; }
    __syncthreads();
    float tot=0.f,tot2=0.f;
#pragma unroll
    for(int i=0;i<8;i++){ tot+=ss[i]; tot2+=sv[i]; }
    float mu=tot*(1.f/1024.f),var=tot2*(1.f/1024.f)-mu*mu;
    float is=rsqrtf(var+1e-5f);
    for(int i=tid;i<1024;i+=256)
        out[(size_t)s*1024+i]=(r[i]-mu)*is*gamma[i]+beta[i];
}

extern "C" void kernel_launch(void* const* d_in,const int* in_sizes,int n_in,
                              void* d_out,int out_size){
    const float* x    =(const float*)d_in[0];
    const float* Wq   =(const float*)d_in[1];
    const float* Wk   =(const float*)d_in[2];
    const float* Wcb  =(const float*)d_in[3];
    const float* Wv   =(const float*)d_in[4];
    const float* bv   =(const float*)d_in[5];
    const float* mixing=(const float*)d_in[6];
    const float* Wd   =(const float*)d_in[7];
    const float* bd   =(const float*)d_in[8];
    const float* gamma=(const float*)d_in[9];
    const float* beta =(const float*)d_in[10];
    float* out=(float*)d_out;

    void *xb,*wqb,*wkb,*wvb,*wdb,*mixb,*qb,*kb,*vb,*ctxb,*resp;
    cudaGetSymbolAddress(&xb ,g_xb );
    cudaGetSymbolAddress(&wqb,g_Wqb);
    cudaGetSymbolAddress(&wkb,g_Wkb);
    cudaGetSymbolAddress(&wvb,g_Wvb);
    cudaGetSymbolAddress(&wdb,g_Wdb);
    cudaGetSymbolAddress(&mixb,g_mixb);
    cudaGetSymbolAddress(&qb ,g_q  );
    cudaGetSymbolAddress(&kb ,g_k  );
    cudaGetSymbolAddress(&vb ,g_v  );
    cudaGetSymbolAddress(&ctxb,g_ctx);
    cudaGetSymbolAddress(&resp,g_res);

    cvt_k<<<16384,256>>>(x,(__nv_bfloat16*)xb,BSx*DKx);
    cvt_k<<<4096,256>>>(Wq,(__nv_bfloat16*)wqb,DKx*DKx);
    cvt_k<<<4096,256>>>(Wk,(__nv_bfloat16*)wkb,DKx*DKx);
    cvt_k<<<4096,256>>>(Wv,(__nv_bfloat16*)wvb,DKx*DKx);
    cvt_k<<<4096,256>>>(Wd,(__nv_bfloat16*)wdb,DKx*DKx);
    cvt_k<<<64,256>>>(mixing,(__nv_bfloat16*)mixb,HH*DKx);

    dim3 gg(32,8);
    gemm_k<<<gg,256>>>((const __nv_bfloat16*)xb,(const __nv_bfloat16*)wqb,nullptr,nullptr,qb,0);
    gemm_k<<<gg,256>>>((const __nv_bfloat16*)xb,(const __nv_bfloat16*)wkb,nullptr,nullptr,kb,0);
    gemm_k<<<gg,256>>>((const __nv_bfloat16*)xb,(const __nv_bfloat16*)wvb,bv,nullptr,vb,0);
    cb_k<<<BSx,128>>>(x,Wcb);
    flash_k<<<dim3(16,HH,BB),256>>>();
    gemm_k<<<gg,256>>>((const __nv_bfloat16*)ctxb,(const __nv_bfloat16*)wdb,bd,x,resp,2);
    ln_k<<<BSx,256>>>(gamma,beta,out);
}